// round 1
// baseline (speedup 1.0000x reference)
#include <cuda_runtime.h>
#include <cstdint>

#define EPS_BN 1e-5f

// Folded parameters (device scratch — no allocations allowed)
__device__ float d_Wf[16 * 768];   // conv1 weight * bn1 scale, [c][k] k = ch*256+dy*16+dx
__device__ float d_t1[16];         // b1*s1 + beta1 - m1*s1
__device__ float d_W2f[64];        // w2[o][c] * s2[o]
__device__ float d_t2[4];          // b2*s2 + beta2 - m2*s2
__device__ float d_w3v[4];
__device__ float d_b3v;

__global__ void prep_kernel(const float* __restrict__ w1, const float* __restrict__ b1,
                            const float* __restrict__ g1, const float* __restrict__ be1,
                            const float* __restrict__ m1, const float* __restrict__ v1,
                            const float* __restrict__ w2, const float* __restrict__ b2,
                            const float* __restrict__ g2, const float* __restrict__ be2,
                            const float* __restrict__ m2, const float* __restrict__ v2,
                            const float* __restrict__ w3, const float* __restrict__ b3) {
    int t = blockIdx.x * 256 + threadIdx.x;
    if (t < 16 * 768) {
        int c = t / 768;
        float s1 = g1[c] * rsqrtf(v1[c] + EPS_BN);
        d_Wf[t] = w1[t] * s1;
    }
    if (t < 16) {
        float s1 = g1[t] * rsqrtf(v1[t] + EPS_BN);
        d_t1[t] = b1[t] * s1 + be1[t] - m1[t] * s1;
    }
    if (t < 64) {
        int o = t >> 4;
        float s2 = g2[o] * rsqrtf(v2[o] + EPS_BN);
        d_W2f[t] = w2[t] * s2;
    }
    if (t < 4) {
        float s2 = g2[t] * rsqrtf(v2[t] + EPS_BN);
        d_t2[t] = b2[t] * s2 + be2[t] - m2[t] * s2;
        d_w3v[t] = w3[t];
    }
    if (t == 0) d_b3v = b3[0];
}

// Packed f32x2 FMA: 2 fp32 FMAs per instruction (only reachable via PTX)
__device__ __forceinline__ void ffma2(unsigned long long& a, unsigned long long x,
                                      unsigned long long w) {
    asm("fma.rn.f32x2 %0, %1, %2, %0;" : "+l"(a) : "l"(x), "l"(w));
}
__device__ __forceinline__ float hsum2(unsigned long long a) {
    unsigned lo, hi;
    asm("mov.b64 {%0,%1}, %2;" : "=r"(lo), "=r"(hi) : "l"(a));
    return __uint_as_float(lo) + __uint_as_float(hi);
}

static constexpr int SSTRIDE = 260;  // 256 + 4 pad: kills 3072B==0 mod 128 bank alias

// One block = (batch b, patch-row ph, half) -> 16 patches (pw = half*16 .. +15)
__global__ void __launch_bounds__(256, 2)
cnn_kernel(const float* __restrict__ in, float* __restrict__ out) {
    extern __shared__ float smem[];
    float* sh_in   = smem;                 // 48 * 260 = 12480 floats
    float* sh_part = smem + 12480;         // 16 patches * 8 warps * 16 ch = 2048
    float* sh_r1   = sh_part + 2048;       // 16 * 16
    float* sh_res  = sh_r1 + 256;          // 16

    const int t    = threadIdx.x;
    const int blk  = blockIdx.x;
    const int half = blk & 1;
    const int ph   = (blk >> 1) & 31;
    const int b    = blk >> 6;

    const float* gin = in + (size_t)b * 786432 + (size_t)ph * 8192 + half * 256;

    // Stage input strip: 48 rows (= ch*16 + dy) x 256 floats, coalesced float4
#pragma unroll
    for (int i = 0; i < 12; i++) {
        int idx  = i * 256 + t;      // 0..3071
        int row  = idx >> 6;         // 0..47
        int col4 = idx & 63;
        const float4 v = *reinterpret_cast<const float4*>(
            gin + (size_t)(row >> 4) * 262144 + (row & 15) * 512 + col4 * 4);
        *reinterpret_cast<float4*>(sh_in + row * SSTRIDE + col4 * 4) = v;
    }

    // Thread role: q = position chunk (24 elems), cp -> channels cp and cp+8
    const int q     = t >> 3;   // 0..31
    const int cp    = t & 7;    // 0..7
    const int kbase = q * 24;

    unsigned long long wA[12], wB[12];
    {
        const ulonglong2* wpA = reinterpret_cast<const ulonglong2*>(d_Wf + cp * 768 + kbase);
        const ulonglong2* wpB = reinterpret_cast<const ulonglong2*>(d_Wf + (cp + 8) * 768 + kbase);
#pragma unroll
        for (int g = 0; g < 6; g++) {
            ulonglong2 a = wpA[g]; wA[2 * g] = a.x; wA[2 * g + 1] = a.y;
            ulonglong2 c = wpB[g]; wB[2 * g] = c.x; wB[2 * g + 1] = c.y;
        }
    }

    int soff[6];
#pragma unroll
    for (int g = 0; g < 6; g++) {
        int k = kbase + 4 * g;
        soff[g] = (k >> 4) * SSTRIDE + (k & 15);
    }

    __syncthreads();

    const int warp = t >> 5;
    const int lane = t & 31;

    for (int p = 0; p < 16; p++) {
        unsigned long long accA = 0ull, accB = 0ull;  // (0.f, 0.f) packed
#pragma unroll
        for (int g = 0; g < 6; g++) {
            ulonglong2 x = *reinterpret_cast<const ulonglong2*>(sh_in + soff[g] + p * 16);
            ffma2(accA, x.x, wA[2 * g]);
            ffma2(accA, x.y, wA[2 * g + 1]);
            ffma2(accB, x.x, wB[2 * g]);
            ffma2(accB, x.y, wB[2 * g + 1]);
        }
        float sA = hsum2(accA);
        float sB = hsum2(accB);
        // reduce over the 4 q-chunks held by this warp (bits 3,4 of lane)
        sA += __shfl_xor_sync(0xffffffffu, sA, 8);
        sA += __shfl_xor_sync(0xffffffffu, sA, 16);
        sB += __shfl_xor_sync(0xffffffffu, sB, 8);
        sB += __shfl_xor_sync(0xffffffffu, sB, 16);
        if (lane < 8) {
            sh_part[(p * 8 + warp) * 16 + cp]     = sA;
            sh_part[(p * 8 + warp) * 16 + cp + 8] = sB;
        }
    }
    __syncthreads();

    // Per (patch, channel): sum 8 warp-partials, add t1, ReLU
    {
        int p = t >> 4, c = t & 15;
        float y = d_t1[c];
#pragma unroll
        for (int w = 0; w < 8; w++) y += sh_part[(p * 8 + w) * 16 + c];
        sh_r1[p * 16 + c] = fmaxf(y, 0.0f);
    }
    __syncthreads();

    // 16->4->1 funnel: one thread per patch
    if (t < 16) {
        float z0 = d_t2[0], z1 = d_t2[1], z2 = d_t2[2], z3 = d_t2[3];
#pragma unroll
        for (int c = 0; c < 16; c++) {
            float r = sh_r1[t * 16 + c];
            z0 = fmaf(r, d_W2f[c],      z0);
            z1 = fmaf(r, d_W2f[16 + c], z1);
            z2 = fmaf(r, d_W2f[32 + c], z2);
            z3 = fmaf(r, d_W2f[48 + c], z3);
        }
        float o = d_b3v;
        o = fmaf(fmaxf(z0, 0.f), d_w3v[0], o);
        o = fmaf(fmaxf(z1, 0.f), d_w3v[1], o);
        o = fmaf(fmaxf(z2, 0.f), d_w3v[2], o);
        o = fmaf(fmaxf(z3, 0.f), d_w3v[3], o);
        sh_res[t] = o;
    }
    __syncthreads();

    // 16x nearest upsample write: 16 rows x 256 cols, coalesced float4 broadcast
    float* gout = out + (size_t)b * 262144 + (size_t)ph * 8192 + half * 256;
#pragma unroll
    for (int i = 0; i < 4; i++) {
        int idx  = i * 256 + t;   // 0..1023
        int row  = idx >> 6;      // 0..15
        int col4 = idx & 63;
        float v = sh_res[col4 >> 2];
        *reinterpret_cast<float4*>(gout + row * 512 + col4 * 4) = make_float4(v, v, v, v);
    }
}

extern "C" void kernel_launch(void* const* d_in, const int* in_sizes, int n_in,
                              void* d_out, int out_size) {
    (void)in_sizes; (void)n_in; (void)out_size;
    const float* in = (const float*)d_in[0];

    prep_kernel<<<48, 256>>>(
        (const float*)d_in[1],  (const float*)d_in[2],  (const float*)d_in[3],
        (const float*)d_in[4],  (const float*)d_in[5],  (const float*)d_in[6],
        (const float*)d_in[7],  (const float*)d_in[8],  (const float*)d_in[9],
        (const float*)d_in[10], (const float*)d_in[11], (const float*)d_in[12],
        (const float*)d_in[13], (const float*)d_in[14]);

    const int smem_bytes = 14800 * sizeof(float);  // 59200 B
    cudaFuncSetAttribute(cnn_kernel, cudaFuncAttributeMaxDynamicSharedMemorySize, smem_bytes);
    cnn_kernel<<<2048, 256, smem_bytes>>>(in, (float*)d_out);
}

// round 2
// speedup vs baseline: 1.0734x; 1.0734x over previous
#include <cuda_runtime.h>
#include <cstdint>

#define EPS_BN 1e-5f

// ---------------- folded / repacked parameters (device scratch) ----------------
__device__ unsigned long long d_wd[384 * 16];  // wd[kp][c] = (Wf[c][2kp], Wf[c][2kp+1]) packed f32x2
__device__ float d_t1[16];                     // conv1 bias folded with bn1
__device__ float d_W2f[64];                    // w2[o][c] * s2[o]
__device__ float d_t2[4];
__device__ float d_w3v[4];
__device__ float d_b3v;

__device__ __forceinline__ unsigned long long pack2(float a, float b) {
    return ((unsigned long long)__float_as_uint(b) << 32) | (unsigned long long)__float_as_uint(a);
}

__global__ void prep_kernel(const float* __restrict__ w1, const float* __restrict__ b1,
                            const float* __restrict__ g1, const float* __restrict__ be1,
                            const float* __restrict__ m1, const float* __restrict__ v1,
                            const float* __restrict__ w2, const float* __restrict__ b2,
                            const float* __restrict__ g2, const float* __restrict__ be2,
                            const float* __restrict__ m2, const float* __restrict__ v2,
                            const float* __restrict__ w3, const float* __restrict__ b3) {
    int t = blockIdx.x * 256 + threadIdx.x;
    if (t < 6144) {
        int kp = t >> 4, c = t & 15;
        float s1 = g1[c] * rsqrtf(v1[c] + EPS_BN);
        float a = w1[c * 768 + 2 * kp]     * s1;
        float d = w1[c * 768 + 2 * kp + 1] * s1;
        d_wd[kp * 16 + c] = pack2(a, d);
    }
    if (t < 16) {
        float s1 = g1[t] * rsqrtf(v1[t] + EPS_BN);
        d_t1[t] = b1[t] * s1 + be1[t] - m1[t] * s1;
    }
    if (t < 64) {
        int o = t >> 4;
        float s2 = g2[o] * rsqrtf(v2[o] + EPS_BN);
        d_W2f[t] = w2[t] * s2;
    }
    if (t < 4) {
        float s2 = g2[t] * rsqrtf(v2[t] + EPS_BN);
        d_t2[t] = b2[t] * s2 + be2[t] - m2[t] * s2;
        d_w3v[t] = w3[t];
    }
    if (t == 0) d_b3v = b3[0];
}

// ---------------- packed f32x2 helpers ----------------
__device__ __forceinline__ void ffma2(unsigned long long& a, unsigned long long x,
                                      unsigned long long w) {
    asm("fma.rn.f32x2 %0, %1, %2, %0;" : "+l"(a) : "l"(x), "l"(w));
}
__device__ __forceinline__ unsigned long long add2(unsigned long long a, unsigned long long b) {
    unsigned long long r;
    asm("add.rn.f32x2 %0, %1, %2;" : "=l"(r) : "l"(a), "l"(b));
    return r;
}
__device__ __forceinline__ float hsum2(unsigned long long a) {
    unsigned lo, hi;
    asm("mov.b64 {%0,%1}, %2;" : "=r"(lo), "=r"(hi) : "l"(a));
    return __uint_as_float(lo) + __uint_as_float(hi);
}

// Strip per CTA: (batch b, patch-row ph) -> 32 patches. 128 threads.
// Thread roles: kc = t>>4 (k-split 8), cg = (t>>3)&1 (8 channels), pg = t&7 (4 patches).
// Staged x: sh[kp_local][patch] as float2 (k-pair), row stride 34 (16B-aligned, low conflict).
static constexpr int XSTRIDE = 34;            // in u64/float2 slots
static constexpr int SMEM_SLOTS = 192 * XSTRIDE;  // 6528 float2 = 52224 B

__global__ void __launch_bounds__(128, 4)
cnn_kernel(const float* __restrict__ in, float* __restrict__ out) {
    extern __shared__ float2 shx[];

    const int t  = threadIdx.x;
    const int kc = t >> 4;
    const int cg = (t >> 3) & 1;
    const int pg = t & 7;
    const int blk = blockIdx.x;
    const int ph = blk & 31;
    const int b  = blk >> 5;

    const float* gin = in + (size_t)b * 786432 + (size_t)ph * 16 * 512;

    unsigned long long acc[32];
#pragma unroll
    for (int i = 0; i < 32; i++) acc[i] = 0ull;

    const unsigned long long* shu = (const unsigned long long*)shx;

    for (int cn = 0; cn < 2; cn++) {
        // ---- stage 24 global rows (k = cn*384 .. +383) transposed into k-pair layout ----
#pragma unroll
        for (int it = 0; it < 24; it++) {
            int idx  = it * 128 + t;
            int r    = idx >> 7;          // 0..23
            int col4 = idx & 127;
            int rg   = cn * 24 + r;       // global (ch,dy) row 0..47
            int ch   = rg >> 4, dy = rg & 15;
            const float4 v = *reinterpret_cast<const float4*>(
                gin + (size_t)ch * 262144 + dy * 512 + col4 * 4);
            int p   = col4 >> 2;
            int dxq = col4 & 3;
            int kpl = r * 8 + dxq * 2;    // local k-pair row
            shx[kpl * XSTRIDE + p]       = make_float2(v.x, v.y);
            shx[(kpl + 1) * XSTRIDE + p] = make_float2(v.z, v.w);
        }
        __syncthreads();

        // ---- main loop: 24 k-pair iterations (kp = 8*i + kc) ----
#pragma unroll 4
        for (int i = 0; i < 24; i++) {
            int kpl = i * 8 + kc;
            int kpg = cn * 192 + kpl;

            const ulonglong2* xp = reinterpret_cast<const ulonglong2*>(shu + kpl * XSTRIDE + pg * 4);
            ulonglong2 x01 = xp[0];
            ulonglong2 x23 = xp[1];
            unsigned long long xv[4] = {x01.x, x01.y, x23.x, x23.y};

            const ulonglong2* wp = reinterpret_cast<const ulonglong2*>(d_wd + kpg * 16 + cg * 8);
            ulonglong2 w01 = __ldg(wp);
            ulonglong2 w23 = __ldg(wp + 1);
            ulonglong2 w45 = __ldg(wp + 2);
            ulonglong2 w67 = __ldg(wp + 3);
            unsigned long long wv[8] = {w01.x, w01.y, w23.x, w23.y, w45.x, w45.y, w67.x, w67.y};

#pragma unroll
            for (int c = 0; c < 8; c++)
#pragma unroll
                for (int p = 0; p < 4; p++)
                    ffma2(acc[c * 4 + p], xv[p], wv[c]);
        }
        __syncthreads();
    }

    // ---- reduce kc parity in-warp (lane bit 4 = kc&1) ----
#pragma unroll
    for (int i = 0; i < 32; i++) {
        unsigned long long o = __shfl_xor_sync(0xffffffffu, acc[i], 16);
        acc[i] = add2(acc[i], o);
    }

    unsigned long long* shp = (unsigned long long*)shx;
    const int lane = t & 31, wrp = t >> 5;
    if (lane < 16) {
#pragma unroll
        for (int i = 0; i < 32; i++) shp[wrp * 512 + lane * 32 + i] = acc[i];
    }
    __syncthreads();

    float* shr1  = (float*)(shp + 2048);  // 512 floats: [patch][16 ch], post-BN+ReLU
    float* shres = shr1 + 512;            // 32 floats: final scalar per patch

    // ---- final reduce over 4 warps + bias + ReLU ----
#pragma unroll
    for (int j = 0; j < 4; j++) {
        int f = t * 4 + j;
        unsigned long long s = add2(add2(shp[f], shp[512 + f]),
                                    add2(shp[1024 + f], shp[1536 + f]));
        int cgf = f >> 8, pgf = (f >> 5) & 7, ci = (f >> 2) & 7, pi = f & 3;
        int chn = cgf * 8 + ci;
        int pat = pgf * 4 + pi;
        float vsum = hsum2(s) + d_t1[chn];
        shr1[pat * 16 + chn] = fmaxf(vsum, 0.0f);
    }
    __syncthreads();

    // ---- 16->4->1 funnel, one thread per patch ----
    if (t < 32) {
        float z0 = d_t2[0], z1 = d_t2[1], z2 = d_t2[2], z3 = d_t2[3];
#pragma unroll
        for (int c = 0; c < 16; c++) {
            float r = shr1[t * 16 + c];
            z0 = fmaf(r, d_W2f[c],      z0);
            z1 = fmaf(r, d_W2f[16 + c], z1);
            z2 = fmaf(r, d_W2f[32 + c], z2);
            z3 = fmaf(r, d_W2f[48 + c], z3);
        }
        float o = d_b3v;
        o = fmaf(fmaxf(z0, 0.f), d_w3v[0], o);
        o = fmaf(fmaxf(z1, 0.f), d_w3v[1], o);
        o = fmaf(fmaxf(z2, 0.f), d_w3v[2], o);
        o = fmaf(fmaxf(z3, 0.f), d_w3v[3], o);
        shres[t] = o;
    }
    __syncthreads();

    // ---- 16x nearest upsample write: 16 rows x 512 cols, coalesced float4 ----
    float* gout = out + (size_t)b * 262144 + (size_t)ph * 16 * 512;
#pragma unroll
    for (int it = 0; it < 16; it++) {
        int idx  = it * 128 + t;
        int row  = idx >> 7;
        int col4 = idx & 127;
        float v = shres[col4 >> 2];
        *reinterpret_cast<float4*>(gout + row * 512 + col4 * 4) = make_float4(v, v, v, v);
    }
}

extern "C" void kernel_launch(void* const* d_in, const int* in_sizes, int n_in,
                              void* d_out, int out_size) {
    (void)in_sizes; (void)n_in; (void)out_size;
    const float* in = (const float*)d_in[0];

    prep_kernel<<<24, 256>>>(
        (const float*)d_in[1],  (const float*)d_in[2],  (const float*)d_in[3],
        (const float*)d_in[4],  (const float*)d_in[5],  (const float*)d_in[6],
        (const float*)d_in[7],  (const float*)d_in[8],  (const float*)d_in[9],
        (const float*)d_in[10], (const float*)d_in[11], (const float*)d_in[12],
        (const float*)d_in[13], (const float*)d_in[14]);

    const int smem_bytes = SMEM_SLOTS * sizeof(float2);  // 52224
    cudaFuncSetAttribute(cnn_kernel, cudaFuncAttributeMaxDynamicSharedMemorySize, smem_bytes);
    cnn_kernel<<<1024, 128, smem_bytes>>>(in, (float*)d_out);
}